// round 1
// baseline (speedup 1.0000x reference)
#include <cuda_runtime.h>
#include <cstdint>

#define N_NODES 100000
#define N_EDGES 3200000
#define OUT_STRIDE 352           // 128 + 128 + 64 + 32
#define OUT_STRIDE4 88           // in float4 units

// Scratch for aggregation result (max layer dim = 128). 51.2 MB.
__device__ __align__(16) float g_agg[(size_t)N_NODES * 128];

__device__ __forceinline__ float lrelu(float v) { return v > 0.f ? v : 0.01f * v; }

__device__ __forceinline__ void red_add4(float* p, float4 v) {
    asm volatile("red.global.add.v4.f32 [%0], {%1,%2,%3,%4};"
                 :: "l"(p), "f"(v.x), "f"(v.y), "f"(v.z), "f"(v.w) : "memory");
}

// ---------------------------------------------------------------------------
// Zero the aggregation scratch (n4 float4 elements).
__global__ void zero_agg_kernel(int n4) {
    float4* p = reinterpret_cast<float4*>(g_agg);
    float4 z = make_float4(0.f, 0.f, 0.f, 0.f);
    for (int i = blockIdx.x * blockDim.x + threadIdx.x; i < n4;
         i += gridDim.x * blockDim.x)
        p[i] = z;
}

// ---------------------------------------------------------------------------
// Copy x (N x 128 contiguous) into d_out columns [0,128).
__global__ void copy_x_kernel(const float4* __restrict__ x, float4* __restrict__ out) {
    const int total = N_NODES * 32;
    for (int i = blockIdx.x * blockDim.x + threadIdx.x; i < total;
         i += gridDim.x * blockDim.x) {
        int v = i >> 5;
        int c = i & 31;
        out[(size_t)v * OUT_STRIDE4 + c] = x[i];
    }
}

// ---------------------------------------------------------------------------
// Edge aggregation: g_agg[dst] += attn * h[src].
// One thread = one float4 chunk of one edge. DV4 = D/4 (power of two).
// hs4 = row stride of h in float4 units.
template <int LOGDV4>
__global__ void agg_kernel(const float* __restrict__ h, int hs4,
                           const int* __restrict__ src,
                           const int* __restrict__ dst,
                           const float* __restrict__ attn) {
    constexpr int DV4 = 1 << LOGDV4;
    const float4* h4 = reinterpret_cast<const float4*>(h);
    const int total = N_EDGES << LOGDV4;
    for (int t = blockIdx.x * blockDim.x + threadIdx.x; t < total;
         t += gridDim.x * blockDim.x) {
        int e = t >> LOGDV4;
        int c = t & (DV4 - 1);
        int s = __ldg(&src[e]);
        int d = __ldg(&dst[e]);
        float a = __ldg(&attn[e]);
        float4 v = h4[(size_t)s * hs4 + c];
        v.x *= a; v.y *= a; v.z *= a; v.w *= a;
        red_add4(g_agg + (((size_t)d << LOGDV4) + c) * 4, v);
    }
}

// ---------------------------------------------------------------------------
// Bi-interaction fuse:
//   out = lrelu((x + h) @ W1 + b1) + lrelu((x * h) @ W2 + b2)
// x: strided input rows (xs4 float4 stride). h: g_agg (contiguous, IN floats).
// out: pointer already offset to the target column; row stride os4 float4.
// W1, W2 cached in dynamic shared memory. One thread owns 4 output columns.
template <int IN, int OUT>
__global__ void fuse_kernel(const float* __restrict__ x, int xs4,
                            const float* __restrict__ W1, const float* __restrict__ b1,
                            const float* __restrict__ W2, const float* __restrict__ b2,
                            float* __restrict__ out, int os4) {
    constexpr int IN4 = IN / 4;
    constexpr int OUT4 = OUT / 4;
    extern __shared__ float sw[];
    float* sW1 = sw;
    float* sW2 = sw + IN * OUT;
    for (int i = threadIdx.x; i < IN * OUT; i += blockDim.x) {
        sW1[i] = W1[i];
        sW2[i] = W2[i];
    }
    __syncthreads();

    const float4* sW1_4 = reinterpret_cast<const float4*>(sW1);
    const float4* sW2_4 = reinterpret_cast<const float4*>(sW2);
    const float4* b1_4 = reinterpret_cast<const float4*>(b1);
    const float4* b2_4 = reinterpret_cast<const float4*>(b2);

    const int total = N_NODES * OUT4;
    for (int item = blockIdx.x * blockDim.x + threadIdx.x; item < total;
         item += gridDim.x * blockDim.x) {
        int v = item / OUT4;
        int c = item - v * OUT4;
        const float4* xr = reinterpret_cast<const float4*>(x) + (size_t)v * xs4;
        const float4* hr = reinterpret_cast<const float4*>(g_agg) + (size_t)v * IN4;
        float4 a1 = b1_4[c];
        float4 a2 = b2_4[c];
#pragma unroll
        for (int k4 = 0; k4 < IN4; k4++) {
            float4 xv = xr[k4];
            float4 hv = hr[k4];
            float xs_[4] = {xv.x, xv.y, xv.z, xv.w};
            float hs_[4] = {hv.x, hv.y, hv.z, hv.w};
#pragma unroll
            for (int j = 0; j < 4; j++) {
                int k = k4 * 4 + j;
                float s = xs_[j] + hs_[j];
                float p = xs_[j] * hs_[j];
                float4 w1 = sW1_4[k * OUT4 + c];
                float4 w2 = sW2_4[k * OUT4 + c];
                a1.x += s * w1.x; a1.y += s * w1.y;
                a1.z += s * w1.z; a1.w += s * w1.w;
                a2.x += p * w2.x; a2.y += p * w2.y;
                a2.z += p * w2.z; a2.w += p * w2.w;
            }
        }
        float4 r;
        r.x = lrelu(a1.x) + lrelu(a2.x);
        r.y = lrelu(a1.y) + lrelu(a2.y);
        r.z = lrelu(a1.z) + lrelu(a2.z);
        r.w = lrelu(a1.w) + lrelu(a2.w);
        reinterpret_cast<float4*>(out)[(size_t)v * os4 + c] = r;
    }
}

// ---------------------------------------------------------------------------
extern "C" void kernel_launch(void* const* d_in, const int* in_sizes, int n_in,
                              void* d_out, int out_size) {
    const float* x    = (const float*)d_in[0];
    const int*   src  = (const int*)d_in[1];
    const int*   dst  = (const int*)d_in[2];
    const float* attn = (const float*)d_in[3];
    const float* W1_0 = (const float*)d_in[4];
    const float* b1_0 = (const float*)d_in[5];
    const float* W2_0 = (const float*)d_in[6];
    const float* b2_0 = (const float*)d_in[7];
    const float* W1_1 = (const float*)d_in[8];
    const float* b1_1 = (const float*)d_in[9];
    const float* W2_1 = (const float*)d_in[10];
    const float* b2_1 = (const float*)d_in[11];
    const float* W1_2 = (const float*)d_in[12];
    const float* b1_2 = (const float*)d_in[13];
    const float* W2_2 = (const float*)d_in[14];
    const float* b2_2 = (const float*)d_in[15];
    float* out = (float*)d_out;

    cudaFuncSetAttribute(fuse_kernel<128, 128>,
                         cudaFuncAttributeMaxDynamicSharedMemorySize, 2 * 128 * 128 * 4);
    cudaFuncSetAttribute(fuse_kernel<128, 64>,
                         cudaFuncAttributeMaxDynamicSharedMemorySize, 2 * 128 * 64 * 4);

    // embs[0] = x -> columns [0, 128)
    copy_x_kernel<<<4096, 256>>>((const float4*)x, (float4*)out);

    // ---- Layer 0: IN=128, OUT=128, input = x (stride 32 float4) ----
    zero_agg_kernel<<<4096, 256>>>(N_NODES * 32);
    agg_kernel<5><<<65536, 256>>>(x, 32, src, dst, attn);
    fuse_kernel<128, 128><<<148, 512, 2 * 128 * 128 * 4>>>(
        x, 32, W1_0, b1_0, W2_0, b2_0, out + 128, OUT_STRIDE4);

    // ---- Layer 1: IN=128, OUT=64, input = out cols [128,256) ----
    zero_agg_kernel<<<4096, 256>>>(N_NODES * 32);
    agg_kernel<5><<<65536, 256>>>(out + 128, OUT_STRIDE4, src, dst, attn);
    fuse_kernel<128, 64><<<444, 512, 2 * 128 * 64 * 4>>>(
        out + 128, OUT_STRIDE4, W1_1, b1_1, W2_1, b2_1, out + 256, OUT_STRIDE4);

    // ---- Layer 2: IN=64, OUT=32, input = out cols [256,320) ----
    zero_agg_kernel<<<4096, 256>>>(N_NODES * 16);
    agg_kernel<4><<<32768, 256>>>(out + 256, OUT_STRIDE4, src, dst, attn);
    fuse_kernel<64, 32><<<592, 512, 2 * 64 * 32 * 4>>>(
        out + 256, OUT_STRIDE4, W1_2, b1_2, W2_2, b2_2, out + 320, OUT_STRIDE4);
}

// round 2
// speedup vs baseline: 1.3249x; 1.3249x over previous
#include <cuda_runtime.h>
#include <cstdint>

#define N_NODES 100000
#define N_EDGES 3200000
#define OUT_STRIDE4 88           // 352 floats / 4

// Scratch for aggregation result (max layer dim = 128). 51.2 MB.
__device__ __align__(16) float g_agg[(size_t)N_NODES * 128];

__device__ __forceinline__ float lrelu(float v) { return v > 0.f ? v : 0.01f * v; }

__device__ __forceinline__ unsigned long long pack2(float a, float b) {
    unsigned long long r;
    asm("mov.b64 %0, {%1,%2};" : "=l"(r) : "f"(a), "f"(b));
    return r;
}
__device__ __forceinline__ void unpack2(unsigned long long v, float& a, float& b) {
    asm("mov.b64 {%0,%1}, %2;" : "=f"(a), "=f"(b) : "l"(v));
}
// Packed fp32x2 FMA (sm_100+; only reachable via PTX, ptxas never auto-fuses).
__device__ __forceinline__ void ffma2(unsigned long long& d,
                                      unsigned long long a, unsigned long long b) {
    asm("fma.rn.f32x2 %0, %1, %2, %0;" : "+l"(d) : "l"(a), "l"(b));
}

__device__ __forceinline__ void red_add4(float* p, float4 v) {
    asm volatile("red.global.add.v4.f32 [%0], {%1,%2,%3,%4};"
                 :: "l"(p), "f"(v.x), "f"(v.y), "f"(v.z), "f"(v.w) : "memory");
}

// ---------------------------------------------------------------------------
__global__ void zero_agg_kernel(int n4) {
    float4* p = reinterpret_cast<float4*>(g_agg);
    float4 z = make_float4(0.f, 0.f, 0.f, 0.f);
    for (int i = blockIdx.x * blockDim.x + threadIdx.x; i < n4;
         i += gridDim.x * blockDim.x)
        p[i] = z;
}

// ---------------------------------------------------------------------------
__global__ void copy_x_kernel(const float4* __restrict__ x, float4* __restrict__ out) {
    const int total = N_NODES * 32;
    for (int i = blockIdx.x * blockDim.x + threadIdx.x; i < total;
         i += gridDim.x * blockDim.x) {
        int v = i >> 5;
        int c = i & 31;
        out[(size_t)v * OUT_STRIDE4 + c] = x[i];
    }
}

// ---------------------------------------------------------------------------
// Edge aggregation: g_agg[dst] += attn * h[src]. One thread = one float4 chunk.
template <int LOGDV4>
__global__ void agg_kernel(const float* __restrict__ h, int hs4,
                           const int* __restrict__ src,
                           const int* __restrict__ dst,
                           const float* __restrict__ attn) {
    constexpr int DV4 = 1 << LOGDV4;
    const float4* h4 = reinterpret_cast<const float4*>(h);
    const int total = N_EDGES << LOGDV4;
    for (int t = blockIdx.x * blockDim.x + threadIdx.x; t < total;
         t += gridDim.x * blockDim.x) {
        int e = t >> LOGDV4;
        int c = t & (DV4 - 1);
        int s = __ldg(&src[e]);
        int d = __ldg(&dst[e]);
        float a = __ldg(&attn[e]);
        float4 v = h4[(size_t)s * hs4 + c];
        v.x *= a; v.y *= a; v.z *= a; v.w *= a;
        red_add4(g_agg + (((size_t)d << LOGDV4) + c) * 4, v);
    }
}

// ---------------------------------------------------------------------------
// Register-blocked bi-interaction fuse with f32x2 packed FMA:
//   out = lrelu((x+h) @ W1 + b1) + lrelu((x*h) @ W2 + b2)
// Block tile: TM rows x OUT cols. Thread: RB rows x 4 cols x 2 GEMMs.
// s,p tiles staged in smem PRE-DUPLICATED ({v,v} pairs) so the inner loop's
// f32x2 broadcast operand is a single LDS.64 (warp-broadcast) with no movs.
template <int IN, int OUT, int TM, int CT>
__global__ __launch_bounds__(256)
void fuse_kernel(const float* __restrict__ x, int xs4,
                 const float* __restrict__ W1, const float* __restrict__ b1,
                 const float* __restrict__ W2, const float* __restrict__ b2,
                 float* __restrict__ out, int os4) {
    constexpr int BK = 16;
    constexpr int RT = 256 / CT;     // row-thread groups
    constexpr int RB = TM / RT;      // rows per thread
    constexpr int IN4 = IN / 4;
    constexpr int OUT4 = OUT / 4;
    constexpr int KS = IN / BK;      // k stages

    __shared__ float sdup[BK][2 * TM];
    __shared__ float pdup[BK][2 * TM];
    __shared__ float w1t[BK][OUT];
    __shared__ float w2t[BK][OUT];

    const int tid = threadIdx.x;
    const int c = tid % CT;          // float4 column this thread owns
    const int tr = tid / CT;         // row group
    const int row0 = blockIdx.x * TM;

    const float4* x4 = reinterpret_cast<const float4*>(x);
    const float4* h4 = reinterpret_cast<const float4*>(g_agg);
    const float4* W1_4 = reinterpret_cast<const float4*>(W1);
    const float4* W2_4 = reinterpret_cast<const float4*>(W2);

    float4 bb1 = reinterpret_cast<const float4*>(b1)[c];
    float4 bb2 = reinterpret_cast<const float4*>(b2)[c];
    unsigned long long a1lo[RB], a1hi[RB], a2lo[RB], a2hi[RB];
#pragma unroll
    for (int r = 0; r < RB; r++) {
        a1lo[r] = pack2(bb1.x, bb1.y); a1hi[r] = pack2(bb1.z, bb1.w);
        a2lo[r] = pack2(bb2.x, bb2.y); a2hi[r] = pack2(bb2.z, bb2.w);
    }

    for (int ks = 0; ks < KS; ks++) {
        const int k0 = ks * BK;
        __syncthreads();   // protect previous stage's tiles
        // ---- stage s/p tiles (duplicated) ----
#pragma unroll 1
        for (int i = tid; i < TM * (BK / 4); i += 256) {
            int rl = i / (BK / 4);
            int kg = i % (BK / 4);
            int gr = row0 + rl;
            if (gr >= N_NODES) gr = N_NODES - 1;
            float4 xv = x4[(size_t)gr * xs4 + (k0 / 4) + kg];
            float4 hv = h4[(size_t)gr * IN4 + (k0 / 4) + kg];
            float xs_[4] = {xv.x, xv.y, xv.z, xv.w};
            float hs_[4] = {hv.x, hv.y, hv.z, hv.w};
#pragma unroll
            for (int j = 0; j < 4; j++) {
                float s = xs_[j] + hs_[j];
                float p = xs_[j] * hs_[j];
                *reinterpret_cast<float2*>(&sdup[kg * 4 + j][2 * rl]) = make_float2(s, s);
                *reinterpret_cast<float2*>(&pdup[kg * 4 + j][2 * rl]) = make_float2(p, p);
            }
        }
        // ---- stage W tiles ----
#pragma unroll 1
        for (int i = tid; i < BK * OUT4; i += 256) {
            int kk = i / OUT4;
            int cc = i - kk * OUT4;
            reinterpret_cast<float4*>(&w1t[kk][0])[cc] =
                W1_4[(size_t)(k0 + kk) * OUT4 + cc];
            reinterpret_cast<float4*>(&w2t[kk][0])[cc] =
                W2_4[(size_t)(k0 + kk) * OUT4 + cc];
        }
        __syncthreads();
        // ---- compute ----
#pragma unroll
        for (int k = 0; k < BK; k++) {
            ulonglong2 w1p = reinterpret_cast<const ulonglong2*>(&w1t[k][0])[c];
            ulonglong2 w2p = reinterpret_cast<const ulonglong2*>(&w2t[k][0])[c];
            const unsigned long long* sr =
                reinterpret_cast<const unsigned long long*>(&sdup[k][2 * tr * RB]);
            const unsigned long long* pr =
                reinterpret_cast<const unsigned long long*>(&pdup[k][2 * tr * RB]);
#pragma unroll
            for (int r = 0; r < RB; r++) {
                unsigned long long s2 = sr[r];
                unsigned long long p2 = pr[r];
                ffma2(a1lo[r], s2, w1p.x);
                ffma2(a1hi[r], s2, w1p.y);
                ffma2(a2lo[r], p2, w2p.x);
                ffma2(a2hi[r], p2, w2p.y);
            }
        }
    }

    // ---- epilogue ----
#pragma unroll
    for (int r = 0; r < RB; r++) {
        int gr = row0 + tr * RB + r;
        if (gr < N_NODES) {
            float v0, v1, v2, v3, u0, u1, u2, u3;
            unpack2(a1lo[r], v0, v1); unpack2(a1hi[r], v2, v3);
            unpack2(a2lo[r], u0, u1); unpack2(a2hi[r], u2, u3);
            float4 o;
            o.x = lrelu(v0) + lrelu(u0);
            o.y = lrelu(v1) + lrelu(u1);
            o.z = lrelu(v2) + lrelu(u2);
            o.w = lrelu(v3) + lrelu(u3);
            reinterpret_cast<float4*>(out)[(size_t)gr * os4 + c] = o;
        }
    }
}

// ---------------------------------------------------------------------------
extern "C" void kernel_launch(void* const* d_in, const int* in_sizes, int n_in,
                              void* d_out, int out_size) {
    const float* x    = (const float*)d_in[0];
    const int*   src  = (const int*)d_in[1];
    const int*   dst  = (const int*)d_in[2];
    const float* attn = (const float*)d_in[3];
    const float* W1_0 = (const float*)d_in[4];
    const float* b1_0 = (const float*)d_in[5];
    const float* W2_0 = (const float*)d_in[6];
    const float* b2_0 = (const float*)d_in[7];
    const float* W1_1 = (const float*)d_in[8];
    const float* b1_1 = (const float*)d_in[9];
    const float* W2_1 = (const float*)d_in[10];
    const float* b2_1 = (const float*)d_in[11];
    const float* W1_2 = (const float*)d_in[12];
    const float* b1_2 = (const float*)d_in[13];
    const float* W2_2 = (const float*)d_in[14];
    const float* b2_2 = (const float*)d_in[15];
    float* out = (float*)d_out;

    // embs[0] = x -> columns [0, 128)
    copy_x_kernel<<<4096, 256>>>((const float4*)x, (float4*)out);

    // ---- Layer 0: IN=128, OUT=128 ----
    zero_agg_kernel<<<4096, 256>>>(N_NODES * 32);
    agg_kernel<5><<<65536, 256>>>(x, 32, src, dst, attn);
    fuse_kernel<128, 128, 64, 32><<<(N_NODES + 63) / 64, 256>>>(
        x, 32, W1_0, b1_0, W2_0, b2_0, out + 128, OUT_STRIDE4);

    // ---- Layer 1: IN=128, OUT=64 ----
    zero_agg_kernel<<<4096, 256>>>(N_NODES * 32);
    agg_kernel<5><<<65536, 256>>>(out + 128, OUT_STRIDE4, src, dst, attn);
    fuse_kernel<128, 64, 64, 16><<<(N_NODES + 63) / 64, 256>>>(
        out + 128, OUT_STRIDE4, W1_1, b1_1, W2_1, b2_1, out + 256, OUT_STRIDE4);

    // ---- Layer 2: IN=64, OUT=32 ----
    zero_agg_kernel<<<4096, 256>>>(N_NODES * 16);
    agg_kernel<4><<<32768, 256>>>(out + 256, OUT_STRIDE4, src, dst, attn);
    fuse_kernel<64, 32, 128, 8><<<(N_NODES + 127) / 128, 256>>>(
        out + 256, OUT_STRIDE4, W1_2, b1_2, W2_2, b2_2, out + 320, OUT_STRIDE4);
}

// round 3
// speedup vs baseline: 1.3534x; 1.0215x over previous
#include <cuda_runtime.h>
#include <cstdint>

#define N_NODES 100000
#define N_EDGES 3200000
#define OUT_STRIDE4 88           // 352 floats / 4

// Scratch for aggregation result (max layer dim = 128). 51.2 MB.
__device__ __align__(16) float g_agg[(size_t)N_NODES * 128];

__device__ __forceinline__ float lrelu(float v) { return v > 0.f ? v : 0.01f * v; }

__device__ __forceinline__ unsigned long long pack2(float a, float b) {
    unsigned long long r;
    asm("mov.b64 %0, {%1,%2};" : "=l"(r) : "f"(a), "f"(b));
    return r;
}
__device__ __forceinline__ void unpack2(unsigned long long v, float& a, float& b) {
    asm("mov.b64 {%0,%1}, %2;" : "=f"(a), "=f"(b) : "l"(v));
}
// Packed fp32x2 FMA (sm_100+; only reachable via PTX).
__device__ __forceinline__ void ffma2(unsigned long long& d,
                                      unsigned long long a, unsigned long long b) {
    asm("fma.rn.f32x2 %0, %1, %2, %0;" : "+l"(d) : "l"(a), "l"(b));
}

__device__ __forceinline__ void red_add4(float* p, float4 v) {
    asm volatile("red.global.add.v4.f32 [%0], {%1,%2,%3,%4};"
                 :: "l"(p), "f"(v.x), "f"(v.y), "f"(v.z), "f"(v.w) : "memory");
}

// ---------------------------------------------------------------------------
__global__ void zero_agg_kernel(int n4) {
    float4* p = reinterpret_cast<float4*>(g_agg);
    float4 z = make_float4(0.f, 0.f, 0.f, 0.f);
    for (int i = blockIdx.x * blockDim.x + threadIdx.x; i < n4;
         i += gridDim.x * blockDim.x)
        p[i] = z;
}

// ---------------------------------------------------------------------------
__global__ void copy_x_kernel(const float4* __restrict__ x, float4* __restrict__ out) {
    const int total = N_NODES * 32;
    for (int i = blockIdx.x * blockDim.x + threadIdx.x; i < total;
         i += gridDim.x * blockDim.x) {
        int v = i >> 5;
        int c = i & 31;
        out[(size_t)v * OUT_STRIDE4 + c] = x[i];
    }
}

// ---------------------------------------------------------------------------
// Edge aggregation: g_agg[dst] += attn * h[src]. One warp = one edge (for
// LOGDV4=5); gather and scatter fully coalesced, indices warp-broadcast.
template <int LOGDV4>
__global__ void agg_kernel(const float* __restrict__ h, int hs4,
                           const int* __restrict__ src,
                           const int* __restrict__ dst,
                           const float* __restrict__ attn) {
    constexpr int DV4 = 1 << LOGDV4;
    const float4* h4 = reinterpret_cast<const float4*>(h);
    const int total = N_EDGES << LOGDV4;
    for (int t = blockIdx.x * blockDim.x + threadIdx.x; t < total;
         t += gridDim.x * blockDim.x) {
        int e = t >> LOGDV4;
        int c = t & (DV4 - 1);
        int s = __ldg(&src[e]);
        int d = __ldg(&dst[e]);
        float a = __ldg(&attn[e]);
        float4 v = h4[(size_t)s * hs4 + c];
        v.x *= a; v.y *= a; v.z *= a; v.w *= a;
        red_add4(g_agg + (((size_t)d << LOGDV4) + c) * 4, v);
    }
}

// ---------------------------------------------------------------------------
// Pipelined register-blocked bi-interaction fuse with f32x2 packed FMA:
//   out = lrelu((x+h) @ W1 + b1) + lrelu((x*h) @ W2 + b2)
// Double-buffered smem stages; next stage prefetched into registers while
// computing the current one (single __syncthreads per stage).
// s,p tiles stored PRE-DUPLICATED ({v,v}) so a single LDS.128 feeds two
// broadcast f32x2 operands with no packing movs.
// Requirements baked in: TM*(BK/4) == 256, BK*(OUT/4) <= 512.
template <int IN, int OUT, int TM, int CT>
__global__ __launch_bounds__(256)
void fuse_kernel(const float* __restrict__ x, int xs4,
                 const float* __restrict__ W1, const float* __restrict__ b1,
                 const float* __restrict__ W2, const float* __restrict__ b2,
                 float* __restrict__ out, int os4) {
    constexpr int BK = 16;
    constexpr int RT = 256 / CT;     // row-thread groups
    constexpr int RB = TM / RT;      // rows per thread (pairs of f32x2 rows)
    constexpr int IN4 = IN / 4;
    constexpr int OUT4 = OUT / 4;
    constexpr int KS = IN / BK;      // k stages
    constexpr int W_IT = (BK * OUT4 + 255) / 256;
    static_assert(TM * (BK / 4) == 256, "staging must be exactly 1 item/thread");

    // dynamic smem layout (floats):
    //   sdup[2][BK][2*TM] | pdup[2][BK][2*TM] | w1t[2][BK][OUT] | w2t[2][BK][OUT]
    extern __shared__ float smem[];
    float* sdup = smem;
    float* pdup = sdup + 2 * BK * 2 * TM;
    float* w1t  = pdup + 2 * BK * 2 * TM;
    float* w2t  = w1t + 2 * BK * OUT;

    const int tid = threadIdx.x;
    const int c = tid % CT;          // float4 column this thread owns
    const int tr = tid / CT;         // row group
    const int row0 = blockIdx.x * TM;

    const float4* x4 = reinterpret_cast<const float4*>(x);
    const float4* h4 = reinterpret_cast<const float4*>(g_agg);
    const float4* W1_4 = reinterpret_cast<const float4*>(W1);
    const float4* W2_4 = reinterpret_cast<const float4*>(W2);

    // staging decomposition (1 item/thread for s/p)
    const int rl = tid / (BK / 4);       // local row 0..TM-1
    const int kg = tid % (BK / 4);       // float4 k-group 0..BK/4-1
    int gr_s = row0 + rl;
    if (gr_s >= N_NODES) gr_s = N_NODES - 1;

    float4 bb1 = reinterpret_cast<const float4*>(b1)[c];
    float4 bb2 = reinterpret_cast<const float4*>(b2)[c];
    unsigned long long a1lo[RB], a1hi[RB], a2lo[RB], a2hi[RB];
#pragma unroll
    for (int r = 0; r < RB; r++) {
        a1lo[r] = pack2(bb1.x, bb1.y); a1hi[r] = pack2(bb1.z, bb1.w);
        a2lo[r] = pack2(bb2.x, bb2.y); a2hi[r] = pack2(bb2.z, bb2.w);
    }

    float4 px, ph;                       // prefetched x/h
    float4 pw1[W_IT], pw2[W_IT];         // prefetched W tiles

    auto load_stage = [&](int ks) {
        const int k0_4 = ks * (BK / 4);
        px = x4[(size_t)gr_s * xs4 + k0_4 + kg];
        ph = h4[(size_t)gr_s * IN4 + k0_4 + kg];
#pragma unroll
        for (int it = 0; it < W_IT; it++) {
            int i = tid + it * 256;
            if (BK * OUT4 % 256 == 0 || i < BK * OUT4) {
                int kk = i / OUT4;
                int cc = i - kk * OUT4;
                pw1[it] = W1_4[(size_t)(ks * BK + kk) * OUT4 + cc];
                pw2[it] = W2_4[(size_t)(ks * BK + kk) * OUT4 + cc];
            }
        }
    };
    auto store_stage = [&](int ks) {
        const int b = ks & 1;
        float* sb = sdup + (size_t)b * BK * 2 * TM;
        float* pb = pdup + (size_t)b * BK * 2 * TM;
        float xs_[4] = {px.x, px.y, px.z, px.w};
        float hs_[4] = {ph.x, ph.y, ph.z, ph.w};
#pragma unroll
        for (int j = 0; j < 4; j++) {
            float s = xs_[j] + hs_[j];
            float p = xs_[j] * hs_[j];
            *reinterpret_cast<float2*>(&sb[(kg * 4 + j) * 2 * TM + 2 * rl]) =
                make_float2(s, s);
            *reinterpret_cast<float2*>(&pb[(kg * 4 + j) * 2 * TM + 2 * rl]) =
                make_float2(p, p);
        }
        float* w1b = w1t + (size_t)b * BK * OUT;
        float* w2b = w2t + (size_t)b * BK * OUT;
#pragma unroll
        for (int it = 0; it < W_IT; it++) {
            int i = tid + it * 256;
            if (BK * OUT4 % 256 == 0 || i < BK * OUT4) {
                int kk = i / OUT4;
                int cc = i - kk * OUT4;
                reinterpret_cast<float4*>(&w1b[kk * OUT])[cc] = pw1[it];
                reinterpret_cast<float4*>(&w2b[kk * OUT])[cc] = pw2[it];
            }
        }
    };
    auto compute_stage = [&](int ks) {
        const int b = ks & 1;
        const float* sb = sdup + (size_t)b * BK * 2 * TM;
        const float* pb = pdup + (size_t)b * BK * 2 * TM;
        const float* w1b = w1t + (size_t)b * BK * OUT;
        const float* w2b = w2t + (size_t)b * BK * OUT;
#pragma unroll
        for (int k = 0; k < BK; k++) {
            ulonglong2 w1p = reinterpret_cast<const ulonglong2*>(&w1b[k * OUT])[c];
            ulonglong2 w2p = reinterpret_cast<const ulonglong2*>(&w2b[k * OUT])[c];
            const ulonglong2* sr =
                reinterpret_cast<const ulonglong2*>(&sb[k * 2 * TM + 2 * tr * RB]);
            const ulonglong2* pr =
                reinterpret_cast<const ulonglong2*>(&pb[k * 2 * TM + 2 * tr * RB]);
#pragma unroll
            for (int r2 = 0; r2 < RB / 2; r2++) {
                ulonglong2 ss = sr[r2];
                ulonglong2 pp = pr[r2];
                ffma2(a1lo[2 * r2], ss.x, w1p.x);
                ffma2(a1hi[2 * r2], ss.x, w1p.y);
                ffma2(a2lo[2 * r2], pp.x, w2p.x);
                ffma2(a2hi[2 * r2], pp.x, w2p.y);
                ffma2(a1lo[2 * r2 + 1], ss.y, w1p.x);
                ffma2(a1hi[2 * r2 + 1], ss.y, w1p.y);
                ffma2(a2lo[2 * r2 + 1], pp.y, w2p.x);
                ffma2(a2hi[2 * r2 + 1], pp.y, w2p.y);
            }
        }
    };

    load_stage(0);
    store_stage(0);
    __syncthreads();
#pragma unroll 1
    for (int ks = 0; ks < KS; ks++) {
        if (ks + 1 < KS) load_stage(ks + 1);
        compute_stage(ks);
        if (ks + 1 < KS) store_stage(ks + 1);
        __syncthreads();
    }

    // ---- epilogue ----
#pragma unroll
    for (int r = 0; r < RB; r++) {
        int gr = row0 + tr * RB + r;
        if (gr < N_NODES) {
            float v0, v1, v2, v3, u0, u1, u2, u3;
            unpack2(a1lo[r], v0, v1); unpack2(a1hi[r], v2, v3);
            unpack2(a2lo[r], u0, u1); unpack2(a2hi[r], u2, u3);
            float4 o;
            o.x = lrelu(v0) + lrelu(u0);
            o.y = lrelu(v1) + lrelu(u1);
            o.z = lrelu(v2) + lrelu(u2);
            o.w = lrelu(v3) + lrelu(u3);
            reinterpret_cast<float4*>(out)[(size_t)gr * os4 + c] = o;
        }
    }
}

// smem bytes for a config
template <int OUT, int TM>
constexpr int fuse_smem() {
    return (2 * 16 * 2 * TM * 2 + 2 * 16 * OUT * 2) * 4;
}

// ---------------------------------------------------------------------------
extern "C" void kernel_launch(void* const* d_in, const int* in_sizes, int n_in,
                              void* d_out, int out_size) {
    const float* x    = (const float*)d_in[0];
    const int*   src  = (const int*)d_in[1];
    const int*   dst  = (const int*)d_in[2];
    const float* attn = (const float*)d_in[3];
    const float* W1_0 = (const float*)d_in[4];
    const float* b1_0 = (const float*)d_in[5];
    const float* W2_0 = (const float*)d_in[6];
    const float* b2_0 = (const float*)d_in[7];
    const float* W1_1 = (const float*)d_in[8];
    const float* b1_1 = (const float*)d_in[9];
    const float* W2_1 = (const float*)d_in[10];
    const float* b2_1 = (const float*)d_in[11];
    const float* W1_2 = (const float*)d_in[12];
    const float* b1_2 = (const float*)d_in[13];
    const float* W2_2 = (const float*)d_in[14];
    const float* b2_2 = (const float*)d_in[15];
    float* out = (float*)d_out;

    constexpr int SM0 = fuse_smem<128, 64>();   // 64 KB
    constexpr int SM1 = fuse_smem<64, 64>();    // 48 KB
    constexpr int SM2 = fuse_smem<32, 64>();    // 40 KB
    cudaFuncSetAttribute(fuse_kernel<128, 128, 64, 32>,
                         cudaFuncAttributeMaxDynamicSharedMemorySize, SM0);
    cudaFuncSetAttribute(fuse_kernel<128, 64, 64, 16>,
                         cudaFuncAttributeMaxDynamicSharedMemorySize, SM1);
    cudaFuncSetAttribute(fuse_kernel<64, 32, 64, 8>,
                         cudaFuncAttributeMaxDynamicSharedMemorySize, SM2);

    // embs[0] = x -> columns [0, 128)
    copy_x_kernel<<<2048, 256>>>((const float4*)x, (float4*)out);

    // ---- Layer 0: IN=128, OUT=128 ----
    zero_agg_kernel<<<2048, 256>>>(N_NODES * 32);
    agg_kernel<5><<<65536, 256>>>(x, 32, src, dst, attn);
    fuse_kernel<128, 128, 64, 32><<<(N_NODES + 63) / 64, 256, SM0>>>(
        x, 32, W1_0, b1_0, W2_0, b2_0, out + 128, OUT_STRIDE4);

    // ---- Layer 1: IN=128, OUT=64 ----
    zero_agg_kernel<<<2048, 256>>>(N_NODES * 32);
    agg_kernel<5><<<65536, 256>>>(out + 128, OUT_STRIDE4, src, dst, attn);
    fuse_kernel<128, 64, 64, 16><<<(N_NODES + 63) / 64, 256, SM1>>>(
        out + 128, OUT_STRIDE4, W1_1, b1_1, W2_1, b2_1, out + 256, OUT_STRIDE4);

    // ---- Layer 2: IN=64, OUT=32 ----
    zero_agg_kernel<<<2048, 256>>>(N_NODES * 16);
    agg_kernel<4><<<32768, 256>>>(out + 256, OUT_STRIDE4, src, dst, attn);
    fuse_kernel<64, 32, 64, 8><<<(N_NODES + 63) / 64, 256, SM2>>>(
        out + 256, OUT_STRIDE4, W1_2, b1_2, W2_2, b2_2, out + 320, OUT_STRIDE4);
}

// round 9
// speedup vs baseline: 2.0135x; 1.4878x over previous
#include <cuda_runtime.h>
#include <cstdint>

#define N_NODES 100000
#define N_EDGES 3200000
#define OUT_STRIDE4 88           // 352 floats / 4
#define SCAN_BLK 1024
#define NB_SCAN ((N_NODES + SCAN_BLK - 1) / SCAN_BLK)   // 98

// Scratch: aggregation result (max dim 128) = 51.2 MB, CSR edges = 25.6 MB.
__device__ __align__(16) float g_agg[(size_t)N_NODES * 128];
__device__ uint2 g_edges[N_EDGES];
__device__ int g_cnt[N_NODES];
__device__ int g_off[N_NODES + 1];
__device__ int g_cur[N_NODES];
__device__ int g_bsum[NB_SCAN];
__device__ int g_boff[NB_SCAN + 1];

__device__ __forceinline__ float lrelu(float v) { return v > 0.f ? v : 0.01f * v; }

__device__ __forceinline__ unsigned long long pack2(float a, float b) {
    unsigned long long r;
    asm("mov.b64 %0, {%1,%2};" : "=l"(r) : "f"(a), "f"(b));
    return r;
}
__device__ __forceinline__ void unpack2(unsigned long long v, float& a, float& b) {
    asm("mov.b64 {%0,%1}, %2;" : "=f"(a), "=f"(b) : "l"(v));
}
__device__ __forceinline__ void ffma2(unsigned long long& d,
                                      unsigned long long a, unsigned long long b) {
    asm("fma.rn.f32x2 %0, %1, %2, %0;" : "+l"(d) : "l"(a), "l"(b));
}

// ---------------------------------------------------------------------------
// CSR build: histogram -> scan -> scatter.
__global__ void zero_cnt_kernel() {
    int i = blockIdx.x * blockDim.x + threadIdx.x;
    if (i < N_NODES) g_cnt[i] = 0;
}
__global__ void hist_kernel(const int* __restrict__ dst) {
    int e = blockIdx.x * blockDim.x + threadIdx.x;
    if (e < N_EDGES) atomicAdd(&g_cnt[dst[e]], 1);
}
__global__ void scan1_kernel() {
    __shared__ int sh[SCAN_BLK];
    int i = blockIdx.x * SCAN_BLK + threadIdx.x;
    int v = (i < N_NODES) ? g_cnt[i] : 0;
    sh[threadIdx.x] = v;
    __syncthreads();
#pragma unroll
    for (int off = 1; off < SCAN_BLK; off <<= 1) {
        int t = (threadIdx.x >= off) ? sh[threadIdx.x - off] : 0;
        __syncthreads();
        sh[threadIdx.x] += t;
        __syncthreads();
    }
    if (i < N_NODES) g_off[i] = sh[threadIdx.x] - v;     // exclusive
    if (threadIdx.x == SCAN_BLK - 1) g_bsum[blockIdx.x] = sh[threadIdx.x];
}
__global__ void scan2_kernel() {
    if (threadIdx.x == 0) {
        int run = 0;
        for (int b = 0; b < NB_SCAN; b++) { g_boff[b] = run; run += g_bsum[b]; }
        g_boff[NB_SCAN] = run;
    }
}
__global__ void scan3_kernel() {
    int i = blockIdx.x * blockDim.x + threadIdx.x;
    if (i < N_NODES) {
        int o = g_off[i] + g_boff[i >> 10];
        g_off[i] = o;
        g_cur[i] = o;
    }
    if (i == N_NODES) g_off[N_NODES] = g_boff[NB_SCAN];
}
__global__ void scatter_kernel(const int* __restrict__ src,
                               const int* __restrict__ dst,
                               const float* __restrict__ attn) {
    int e = blockIdx.x * blockDim.x + threadIdx.x;
    if (e < N_EDGES) {
        int pos = atomicAdd(&g_cur[dst[e]], 1);
        g_edges[pos] = make_uint2((unsigned)src[e], __float_as_uint(attn[e]));
    }
}

// ---------------------------------------------------------------------------
__global__ void copy_x_kernel(const float4* __restrict__ x, float4* __restrict__ out) {
    const int total = N_NODES * 32;
    for (int i = blockIdx.x * blockDim.x + threadIdx.x; i < total;
         i += gridDim.x * blockDim.x) {
        int v = i >> 5;
        int c = i & 31;
        out[(size_t)v * OUT_STRIDE4 + c] = x[i];
    }
}

// ---------------------------------------------------------------------------
// CSR aggregation: g_agg[v] = sum_e attn_e * h[src_e].
// DV4 lanes cooperate on one node (DV4 = D/4); 4-deep accumulator MLP.
template <int LOGDV4>
__global__ __launch_bounds__(256)
void agg_csr_kernel(const float* __restrict__ h, int hs4) {
    constexpr int DV4 = 1 << LOGDV4;
    constexpr int NPW = 32 / DV4;
    const int gw = (blockIdx.x * blockDim.x + threadIdx.x) >> 5;
    const int lane = threadIdx.x & 31;
    const int v = gw * NPW + (lane >> LOGDV4);
    const int c = lane & (DV4 - 1);
    if (v >= N_NODES) return;
    const float4* h4 = reinterpret_cast<const float4*>(h);
    int i = __ldg(&g_off[v]);
    const int end = __ldg(&g_off[v + 1]);
    float4 a0 = make_float4(0, 0, 0, 0), a1 = a0, a2 = a0, a3 = a0;
    for (; i + 4 <= end; i += 4) {
        uint2 e0 = g_edges[i], e1 = g_edges[i + 1];
        uint2 e2 = g_edges[i + 2], e3 = g_edges[i + 3];
        float w0 = __uint_as_float(e0.y), w1 = __uint_as_float(e1.y);
        float w2 = __uint_as_float(e2.y), w3 = __uint_as_float(e3.y);
        float4 v0 = h4[(size_t)e0.x * hs4 + c];
        float4 v1 = h4[(size_t)e1.x * hs4 + c];
        float4 v2 = h4[(size_t)e2.x * hs4 + c];
        float4 v3 = h4[(size_t)e3.x * hs4 + c];
        a0.x += w0 * v0.x; a0.y += w0 * v0.y; a0.z += w0 * v0.z; a0.w += w0 * v0.w;
        a1.x += w1 * v1.x; a1.y += w1 * v1.y; a1.z += w1 * v1.z; a1.w += w1 * v1.w;
        a2.x += w2 * v2.x; a2.y += w2 * v2.y; a2.z += w2 * v2.z; a2.w += w2 * v2.w;
        a3.x += w3 * v3.x; a3.y += w3 * v3.y; a3.z += w3 * v3.z; a3.w += w3 * v3.w;
    }
    for (; i < end; i++) {
        uint2 e0 = g_edges[i];
        float w0 = __uint_as_float(e0.y);
        float4 v0 = h4[(size_t)e0.x * hs4 + c];
        a0.x += w0 * v0.x; a0.y += w0 * v0.y; a0.z += w0 * v0.z; a0.w += w0 * v0.w;
    }
    float4 s;
    s.x = (a0.x + a1.x) + (a2.x + a3.x);
    s.y = (a0.y + a1.y) + (a2.y + a3.y);
    s.z = (a0.z + a1.z) + (a2.z + a3.z);
    s.w = (a0.w + a1.w) + (a2.w + a3.w);
    reinterpret_cast<float4*>(g_agg)[(size_t)v * DV4 + c] = s;
}

// ---------------------------------------------------------------------------
// Pipelined register-blocked bi-interaction fuse with f32x2 packed FMA.
template <int IN, int OUT, int TM, int CT>
__global__ __launch_bounds__(256, 2)
void fuse_kernel(const float* __restrict__ x, int xs4,
                 const float* __restrict__ W1, const float* __restrict__ b1,
                 const float* __restrict__ W2, const float* __restrict__ b2,
                 float* __restrict__ out, int os4) {
    constexpr int BK = 16;
    constexpr int RT = 256 / CT;
    constexpr int RB = TM / RT;
    constexpr int IN4 = IN / 4;
    constexpr int OUT4 = OUT / 4;
    constexpr int KS = IN / BK;
    constexpr int W_IT = (BK * OUT4 + 255) / 256;
    static_assert(TM * (BK / 4) == 256, "staging must be exactly 1 item/thread");

    extern __shared__ float smem[];
    float* sdup = smem;
    float* pdup = sdup + 2 * BK * 2 * TM;
    float* w1t  = pdup + 2 * BK * 2 * TM;
    float* w2t  = w1t + 2 * BK * OUT;

    const int tid = threadIdx.x;
    const int c = tid % CT;
    const int tr = tid / CT;
    const int row0 = blockIdx.x * TM;

    const float4* x4 = reinterpret_cast<const float4*>(x);
    const float4* h4 = reinterpret_cast<const float4*>(g_agg);
    const float4* W1_4 = reinterpret_cast<const float4*>(W1);
    const float4* W2_4 = reinterpret_cast<const float4*>(W2);

    const int rl = tid / (BK / 4);
    const int kg = tid % (BK / 4);
    int gr_s = row0 + rl;
    if (gr_s >= N_NODES) gr_s = N_NODES - 1;

    float4 bb1 = reinterpret_cast<const float4*>(b1)[c];
    float4 bb2 = reinterpret_cast<const float4*>(b2)[c];
    unsigned long long a1lo[RB], a1hi[RB], a2lo[RB], a2hi[RB];
#pragma unroll
    for (int r = 0; r < RB; r++) {
        a1lo[r] = pack2(bb1.x, bb1.y); a1hi[r] = pack2(bb1.z, bb1.w);
        a2lo[r] = pack2(bb2.x, bb2.y); a2hi[r] = pack2(bb2.z, bb2.w);
    }

    float4 px, ph;
    float4 pw1[W_IT], pw2[W_IT];

    auto load_stage = [&](int ks) {
        const int k0_4 = ks * (BK / 4);
        px = x4[(size_t)gr_s * xs4 + k0_4 + kg];
        ph = h4[(size_t)gr_s * IN4 + k0_4 + kg];
#pragma unroll
        for (int it = 0; it < W_IT; it++) {
            int i = tid + it * 256;
            if (BK * OUT4 % 256 == 0 || i < BK * OUT4) {
                int kk = i / OUT4;
                int cc = i - kk * OUT4;
                pw1[it] = W1_4[(size_t)(ks * BK + kk) * OUT4 + cc];
                pw2[it] = W2_4[(size_t)(ks * BK + kk) * OUT4 + cc];
            }
        }
    };
    auto store_stage = [&](int ks) {
        const int b = ks & 1;
        float* sb = sdup + (size_t)b * BK * 2 * TM;
        float* pb = pdup + (size_t)b * BK * 2 * TM;
        float xs_[4] = {px.x, px.y, px.z, px.w};
        float hs_[4] = {ph.x, ph.y, ph.z, ph.w};
#pragma unroll
        for (int j = 0; j < 4; j++) {
            float s = xs_[j] + hs_[j];
            float p = xs_[j] * hs_[j];
            *reinterpret_cast<float2*>(&sb[(kg * 4 + j) * 2 * TM + 2 * rl]) =
                make_float2(s, s);
            *reinterpret_cast<float2*>(&pb[(kg * 4 + j) * 2 * TM + 2 * rl]) =
                make_float2(p, p);
        }
        float* w1b = w1t + (size_t)b * BK * OUT;
        float* w2b = w2t + (size_t)b * BK * OUT;
#pragma unroll
        for (int it = 0; it < W_IT; it++) {
            int i = tid + it * 256;
            if (BK * OUT4 % 256 == 0 || i < BK * OUT4) {
                int kk = i / OUT4;
                int cc = i - kk * OUT4;
                reinterpret_cast<float4*>(&w1b[kk * OUT])[cc] = pw1[it];
                reinterpret_cast<float4*>(&w2b[kk * OUT])[cc] = pw2[it];
            }
        }
    };
    auto compute_stage = [&](int ks) {
        const int b = ks & 1;
        const float* sb = sdup + (size_t)b * BK * 2 * TM;
        const float* pb = pdup + (size_t)b * BK * 2 * TM;
        const float* w1b = w1t + (size_t)b * BK * OUT;
        const float* w2b = w2t + (size_t)b * BK * OUT;
#pragma unroll
        for (int k = 0; k < BK; k++) {
            ulonglong2 w1p = reinterpret_cast<const ulonglong2*>(&w1b[k * OUT])[c];
            ulonglong2 w2p = reinterpret_cast<const ulonglong2*>(&w2b[k * OUT])[c];
            const ulonglong2* sr =
                reinterpret_cast<const ulonglong2*>(&sb[k * 2 * TM + 2 * tr * RB]);
            const ulonglong2* pr =
                reinterpret_cast<const ulonglong2*>(&pb[k * 2 * TM + 2 * tr * RB]);
#pragma unroll
            for (int r2 = 0; r2 < RB / 2; r2++) {
                ulonglong2 ss = sr[r2];
                ulonglong2 pp = pr[r2];
                ffma2(a1lo[2 * r2], ss.x, w1p.x);
                ffma2(a1hi[2 * r2], ss.x, w1p.y);
                ffma2(a2lo[2 * r2], pp.x, w2p.x);
                ffma2(a2hi[2 * r2], pp.x, w2p.y);
                ffma2(a1lo[2 * r2 + 1], ss.y, w1p.x);
                ffma2(a1hi[2 * r2 + 1], ss.y, w1p.y);
                ffma2(a2lo[2 * r2 + 1], pp.y, w2p.x);
                ffma2(a2hi[2 * r2 + 1], pp.y, w2p.y);
            }
        }
    };

    load_stage(0);
    store_stage(0);
    __syncthreads();
#pragma unroll 1
    for (int ks = 0; ks < KS; ks++) {
        if (ks + 1 < KS) load_stage(ks + 1);
        compute_stage(ks);
        if (ks + 1 < KS) store_stage(ks + 1);
        __syncthreads();
    }

#pragma unroll
    for (int r = 0; r < RB; r++) {
        int gr = row0 + tr * RB + r;
        if (gr < N_NODES) {
            float v0, v1, v2, v3, u0, u1, u2, u3;
            unpack2(a1lo[r], v0, v1); unpack2(a1hi[r], v2, v3);
            unpack2(a2lo[r], u0, u1); unpack2(a2hi[r], u2, u3);
            float4 o;
            o.x = lrelu(v0) + lrelu(u0);
            o.y = lrelu(v1) + lrelu(u1);
            o.z = lrelu(v2) + lrelu(u2);
            o.w = lrelu(v3) + lrelu(u3);
            reinterpret_cast<float4*>(out)[(size_t)gr * os4 + c] = o;
        }
    }
}

template <int OUT, int TM>
constexpr int fuse_smem() {
    return (2 * 16 * 2 * TM * 2 + 2 * 16 * OUT * 2) * 4;
}

// ---------------------------------------------------------------------------
extern "C" void kernel_launch(void* const* d_in, const int* in_sizes, int n_in,
                              void* d_out, int out_size) {
    const float* x    = (const float*)d_in[0];
    const int*   src  = (const int*)d_in[1];
    const int*   dst  = (const int*)d_in[2];
    const float* attn = (const float*)d_in[3];
    const float* W1_0 = (const float*)d_in[4];
    const float* b1_0 = (const float*)d_in[5];
    const float* W2_0 = (const float*)d_in[6];
    const float* b2_0 = (const float*)d_in[7];
    const float* W1_1 = (const float*)d_in[8];
    const float* b1_1 = (const float*)d_in[9];
    const float* W2_1 = (const float*)d_in[10];
    const float* b2_1 = (const float*)d_in[11];
    const float* W1_2 = (const float*)d_in[12];
    const float* b1_2 = (const float*)d_in[13];
    const float* W2_2 = (const float*)d_in[14];
    const float* b2_2 = (const float*)d_in[15];
    float* out = (float*)d_out;

    constexpr int SM0 = fuse_smem<128, 64>();
    constexpr int SM1 = fuse_smem<64, 64>();
    constexpr int SM2 = fuse_smem<32, 64>();
    cudaFuncSetAttribute(fuse_kernel<128, 128, 64, 32>,
                         cudaFuncAttributeMaxDynamicSharedMemorySize, SM0);
    cudaFuncSetAttribute(fuse_kernel<128, 64, 64, 16>,
                         cudaFuncAttributeMaxDynamicSharedMemorySize, SM1);
    cudaFuncSetAttribute(fuse_kernel<64, 32, 64, 8>,
                         cudaFuncAttributeMaxDynamicSharedMemorySize, SM2);

    // ---- CSR build (once; reused by all 3 layers) ----
    zero_cnt_kernel<<<(N_NODES + 255) / 256, 256>>>();
    hist_kernel<<<(N_EDGES + 255) / 256, 256>>>(dst);
    scan1_kernel<<<NB_SCAN, SCAN_BLK>>>();
    scan2_kernel<<<1, 32>>>();
    scan3_kernel<<<(N_NODES + 256) / 256, 256>>>();
    scatter_kernel<<<(N_EDGES + 255) / 256, 256>>>(src, dst, attn);

    // embs[0] = x -> columns [0, 128)
    copy_x_kernel<<<2048, 256>>>((const float4*)x, (float4*)out);

    // ---- Layer 0: IN=128, OUT=128 ----
    agg_csr_kernel<5><<<(N_NODES * 32 + 255) / 256, 256>>>(x, 32);
    fuse_kernel<128, 128, 64, 32><<<(N_NODES + 63) / 64, 256, SM0>>>(
        x, 32, W1_0, b1_0, W2_0, b2_0, out + 128, OUT_STRIDE4);

    // ---- Layer 1: IN=128, OUT=64 ----
    agg_csr_kernel<5><<<(N_NODES * 32 + 255) / 256, 256>>>(out + 128, OUT_STRIDE4);
    fuse_kernel<128, 64, 64, 16><<<(N_NODES + 63) / 64, 256, SM1>>>(
        out + 128, OUT_STRIDE4, W1_1, b1_1, W2_1, b2_1, out + 256, OUT_STRIDE4);

    // ---- Layer 2: IN=64, OUT=32 ----
    agg_csr_kernel<4><<<(N_NODES * 16 + 255) / 256, 256>>>(out + 256, OUT_STRIDE4);
    fuse_kernel<64, 32, 64, 8><<<(N_NODES + 63) / 64, 256, SM2>>>(
        out + 256, OUT_STRIDE4, W1_2, b1_2, W2_2, b2_2, out + 320, OUT_STRIDE4);
}